// round 7
// baseline (speedup 1.0000x reference)
#include <cuda_runtime.h>
#include <cuda.h>
#include <math.h>

// QuadrotorDynamics: per-row map over (B,16) f32.
// Input row:  [0:3]=ang, [3:6]=pos(unused), [6:9]=rate, [9:12]=vel, [12:16]=cmd
// Output row: [0:3]=ang_dot, [3:6]=vel, [6:9]=rate_dot, [9:12]=vel_dot, [12:16]=0
//
// Persistent TMA kernel, IN-PLACE tiles: each CTA owns two 16KB buffers and
// alternates: TMA-load -> compute in place -> TMA-store -> (read-drain) ->
// TMA-load next. 6 CTAs/SM for deep chip-wide MLP.
//
// Precision note: theta uses PRECISE sincosf because cos(theta) is a
// denominator (rows with theta near pi/2 make 1/c_th ~1e5; __sincosf's
// ~3.6e-7 absolute error there becomes ~3% relative -> fails 1e-3).
// phi/psi only feed numerators/bounded products -> fast __sincosf is safe.

#define C_L      0.17f
#define C_MASS   0.68f
#define C_DARM   0.016f
#define C_KT     0.1f
#define C_KR     0.1f
#define C_IXX    0.007f
#define C_IYY    0.007f
#define C_IZZ    0.012f
#define C_GZ     9.8067f
#define C_707L   (0.707f * C_L)

#define TILE_ROWS   256
#define TILE_BYTES  16384u
#define SMEM_DYN    (2 * 16384 + 1024)   // 2 buffers + alignment slack (<48KB)

// float4-index swizzle == TMA SWIZZLE_128B layout (float4 j of 128B-row r
// goes to j ^ (r&7)).
__device__ __forceinline__ int sw(int idx) { return idx ^ ((idx >> 3) & 7); }

__device__ __forceinline__ void compute_row(
    const float4 x0, const float4 x1, const float4 x2, const float4 x3,
    float a0, float a1, float a2, float a3,
    float b0, float b1, float b2, float b3,
    float c0, float c1_, float c2_, float c3_,
    float4& o0, float4& o1, float4& o2)
{
    // thrusts = a*cmd^2 + b*cmd + c
    const float t0 = fmaf(fmaf(a0, x3.x, b0), x3.x, c0);
    const float t1 = fmaf(fmaf(a1, x3.y, b1), x3.y, c1_);
    const float t2 = fmaf(fmaf(a2, x3.z, b2), x3.z, c2_);
    const float t3 = fmaf(fmaf(a3, x3.w, b3), x3.w, c3_);

    // torques = TORQUE_MAT @ thrusts (constants folded)
    const float tqT = t0 + t1 + t2 + t3;
    const float tq1 = C_707L * ((t0 + t3) - (t1 + t2));
    const float tq2 = C_707L * ((t2 + t3) - (t0 + t1));
    const float tq3 = C_DARM * ((t1 + t3) - (t0 + t2));

    float s_phi, c_phi, s_th, c_th, s_psi, c_psi;
    __sincosf(x0.x, &s_phi, &c_phi);    // phi: numerators only -> fast OK
    sincosf(x0.y, &s_th,  &c_th);       // theta: c_th is a denominator -> PRECISE
    __sincosf(x0.z, &s_psi, &c_psi);    // psi: bounded products -> fast OK

    const float p = x1.z, q = x1.w, r = x2.x;
    const float vx = x2.y, vy = x2.z, vz = x2.w;

    // ang_dot = inv(Mm) @ rate, closed form (det(Mm) = c_th)
    const float y2 = __fdividef(fmaf(s_phi, q, c_phi * r), c_th);
    const float y1 = c_phi * q - s_phi * r;
    const float y0 = fmaf(s_phi, y2, p);

    // rbi third column
    const float z0 = fmaf(c_phi * c_psi, s_th,  s_phi * s_psi);
    const float z1 = fmaf(c_phi * s_psi, s_th, -s_phi * c_psi);
    const float z2 = c_th * c_phi;

    // vel_dot = rbi[:,2]*(T/m) - KT*vel - GRAV
    const float Tm  = tqT * (1.0f / C_MASS);
    const float vd0 = fmaf(z0, Tm, -C_KT * vx);
    const float vd1 = fmaf(z1, Tm, -C_KT * vy);
    const float vd2 = fmaf(z2, Tm, -C_KT * vz) - C_GZ;

    // rate_dot = I_inv @ (tau - w x (I w) - KR*w)   (diagonal I)
    const float rd0 = (tq1 - q * r * (C_IZZ - C_IYY) - C_KR * p) * (1.0f / C_IXX);
    const float rd1 = (tq2 - r * p * (C_IXX - C_IZZ) - C_KR * q) * (1.0f / C_IYY);
    const float rd2 = (tq3 - p * q * (C_IYY - C_IXX) - C_KR * r) * (1.0f / C_IZZ);

    o0 = make_float4(y0,  y1,  y2,  vx);
    o1 = make_float4(vy,  vz,  rd0, rd1);
    o2 = make_float4(rd2, vd0, vd1, vd2);
}

// mbarrier wait with HW-sleep suspend hint (no poll storm).
__device__ __forceinline__ void mbar_wait(unsigned mb, unsigned phase)
{
    unsigned done;
    do {
        asm volatile("{\n\t.reg .pred p;\n\t"
                     "mbarrier.try_wait.parity.acquire.cta.shared::cta.b64 p, [%1], %2, 0x989680;\n\t"
                     "selp.b32 %0, 1, 0, p;\n\t}"
                     : "=r"(done) : "r"(mb), "r"(phase) : "memory");
    } while (!done);
}

__global__ void __launch_bounds__(256, 6)
quad_pipe_kernel(const __grid_constant__ CUtensorMap tmap_in,
                 const __grid_constant__ CUtensorMap tmap_out,
                 const float4* __restrict__ in,
                 float4* __restrict__ out,
                 const float* __restrict__ ga,
                 const float* __restrict__ gb,
                 const float* __restrict__ gc,
                 int n, int ntiles)
{
    extern __shared__ char raw[];
    __shared__ uint64_t mbar_s[2];

    const int tid = threadIdx.x;
    const int G   = gridDim.x;

    // align dynamic smem to 1024 for SW128
    const unsigned rbase = (unsigned)__cvta_generic_to_shared(raw);
    const unsigned abase = (rbase + 1023u) & ~1023u;
    float4* const buf0 = (float4*)(raw + (abase - rbase));
    float4* const buf1 = (float4*)(raw + (abase - rbase) + TILE_BYTES);
    const unsigned mb0 = (unsigned)__cvta_generic_to_shared(&mbar_s[0]);
    const unsigned mb1 = (unsigned)__cvta_generic_to_shared(&mbar_s[1]);

    const float a0 = __ldg(&ga[0]), a1 = __ldg(&ga[1]), a2 = __ldg(&ga[2]), a3 = __ldg(&ga[3]);
    const float b0 = __ldg(&gb[0]), b1 = __ldg(&gb[1]), b2 = __ldg(&gb[2]), b3 = __ldg(&gb[3]);
    const float c0 = __ldg(&gc[0]), c1 = __ldg(&gc[1]), c2 = __ldg(&gc[2]), c3 = __ldg(&gc[3]);

    if (tid == 0) {
        asm volatile("mbarrier.init.shared.b64 [%0], 1;" :: "r"(mb0) : "memory");
        asm volatile("mbarrier.init.shared.b64 [%0], 1;" :: "r"(mb1) : "memory");
        asm volatile("fence.proxy.async.shared::cta;" ::: "memory");
    }
    __syncthreads();

    // prologue: prefetch tiles for iterations 0 and 1
    if (tid == 0) {
        #pragma unroll
        for (int k = 0; k < 2; k++) {
            int tile = blockIdx.x + k * G;
            if (tile < ntiles) {
                unsigned mb  = k ? mb1 : mb0;
                unsigned dst = abase + (unsigned)k * TILE_BYTES;
                asm volatile("mbarrier.arrive.expect_tx.shared.b64 _, [%0], %1;"
                             :: "r"(mb), "r"(TILE_BYTES) : "memory");
                asm volatile("cp.async.bulk.tensor.2d.shared::cta.global.tile.mbarrier::complete_tx::bytes"
                             " [%0], [%1, {%2, %3}], [%4];"
                             :: "r"(dst), "l"(&tmap_in), "r"(0), "r"(tile << 7), "r"(mb)
                             : "memory");
            }
        }
    }

    const int i4 = tid << 2;
    for (int k = 0; ; k++) {
        const int tile = blockIdx.x + k * G;
        if (tile >= ntiles) break;
        const int buf = k & 1;
        const unsigned mb = buf ? mb1 : mb0;
        float4* const s = buf ? buf1 : buf0;

        mbar_wait(mb, (unsigned)((k >> 1) & 1));

        // compute in place: each thread touches only its own 4 slots
        const float4 x0 = s[sw(i4 + 0)];
        const float4 x1 = s[sw(i4 + 1)];
        const float4 x2 = s[sw(i4 + 2)];
        const float4 x3 = s[sw(i4 + 3)];
        float4 o0, o1, o2;
        compute_row(x0, x1, x2, x3, a0,a1,a2,a3, b0,b1,b2,b3, c0,c1,c2,c3, o0, o1, o2);
        s[sw(i4 + 0)] = o0;
        s[sw(i4 + 1)] = o1;
        s[sw(i4 + 2)] = o2;
        s[sw(i4 + 3)] = make_float4(0.0f, 0.0f, 0.0f, 0.0f);
        __syncthreads();   // tile fully transformed

        if (tid == 0) {
            const unsigned bufaddr = abase + (unsigned)buf * TILE_BYTES;
            asm volatile("fence.proxy.async.shared::cta;" ::: "memory");
            asm volatile("cp.async.bulk.tensor.2d.global.shared::cta.tile.bulk_group"
                         " [%0, {%1, %2}], [%3];"
                         :: "l"(&tmap_out), "r"(0), "r"(tile << 7), "r"(bufaddr)
                         : "memory");
            asm volatile("cp.async.bulk.commit_group;" ::: "memory");

            const int nt = tile + 2 * G;
            if (nt < ntiles) {
                // wait until this buffer's store has READ the smem, then reload
                asm volatile("cp.async.bulk.wait_group.read 0;" ::: "memory");
                asm volatile("mbarrier.arrive.expect_tx.shared.b64 _, [%0], %1;"
                             :: "r"(mb), "r"(TILE_BYTES) : "memory");
                asm volatile("cp.async.bulk.tensor.2d.shared::cta.global.tile.mbarrier::complete_tx::bytes"
                             " [%0], [%1, {%2, %3}], [%4];"
                             :: "r"(bufaddr), "l"(&tmap_in), "r"(0), "r"(nt << 7), "r"(mb)
                             : "memory");
            }
        }
        // buffer reuse is guarded by the mbarrier phase; no second sync needed.
    }

    if (tid == 0) {
        asm volatile("cp.async.bulk.wait_group 0;" ::: "memory");
    }

    // remainder rows (n % 256) handled by CTA 0 directly (tiny)
    const int rem = n - ntiles * TILE_ROWS;
    if (blockIdx.x == 0 && tid < rem) {
        const int row = ntiles * TILE_ROWS + tid;
        const float4 x0 = in[4 * row + 0];
        const float4 x1 = in[4 * row + 1];
        const float4 x2 = in[4 * row + 2];
        const float4 x3 = in[4 * row + 3];
        float4 o0, o1, o2;
        compute_row(x0, x1, x2, x3, a0,a1,a2,a3, b0,b1,b2,b3, c0,c1,c2,c3, o0, o1, o2);
        out[4 * row + 0] = o0;
        out[4 * row + 1] = o1;
        out[4 * row + 2] = o2;
        out[4 * row + 3] = make_float4(0.0f, 0.0f, 0.0f, 0.0f);
    }
}

// ---------------------------------------------------------------------------
// Fallback (no TMA): smem-staged kernel.
// ---------------------------------------------------------------------------
__global__ void __launch_bounds__(256)
quad_dyn_kernel(const float4* __restrict__ in,
                float4* __restrict__ out,
                const float* __restrict__ ga,
                const float* __restrict__ gb,
                const float* __restrict__ gc,
                int n)
{
    __shared__ float4 s[1024];
    const int tid = threadIdx.x;
    const int row0 = blockIdx.x << 8;
    const int rows_here = min(256, n - row0);
    const int q_here = rows_here << 2;
    const int gbase = row0 << 2;

    const float a0 = __ldg(&ga[0]), a1 = __ldg(&ga[1]), a2 = __ldg(&ga[2]), a3 = __ldg(&ga[3]);
    const float b0 = __ldg(&gb[0]), b1 = __ldg(&gb[1]), b2 = __ldg(&gb[2]), b3 = __ldg(&gb[3]);
    const float c0 = __ldg(&gc[0]), c1 = __ldg(&gc[1]), c2 = __ldg(&gc[2]), c3 = __ldg(&gc[3]);

    #pragma unroll
    for (int k = 0; k < 4; k++) {
        int idx = tid + (k << 8);
        if (idx < q_here) s[sw(idx)] = in[gbase + idx];
    }
    __syncthreads();

    if (tid < rows_here) {
        const int i4 = tid << 2;
        const float4 x0 = s[sw(i4 + 0)];
        const float4 x1 = s[sw(i4 + 1)];
        const float4 x2 = s[sw(i4 + 2)];
        const float4 x3 = s[sw(i4 + 3)];
        float4 o0, o1, o2;
        compute_row(x0, x1, x2, x3, a0,a1,a2,a3, b0,b1,b2,b3, c0,c1,c2,c3, o0, o1, o2);
        s[sw(i4 + 0)] = o0;
        s[sw(i4 + 1)] = o1;
        s[sw(i4 + 2)] = o2;
        s[sw(i4 + 3)] = make_float4(0.0f, 0.0f, 0.0f, 0.0f);
    }
    __syncthreads();

    #pragma unroll
    for (int k = 0; k < 4; k++) {
        int idx = tid + (k << 8);
        if (idx < q_here) out[gbase + idx] = s[sw(idx)];
    }
}

// ---------------------------------------------------------------------------
// Host side
// ---------------------------------------------------------------------------
typedef CUresult (*EncodeTiledFn)(
    CUtensorMap*, CUtensorMapDataType, cuuint32_t, void*,
    const cuuint64_t*, const cuuint64_t*, const cuuint32_t*, const cuuint32_t*,
    CUtensorMapInterleave, CUtensorMapSwizzle, CUtensorMapL2promotion,
    CUtensorMapFloatOOBfill);

static bool build_map(EncodeTiledFn enc, CUtensorMap* m, void* ptr,
                      unsigned long long rows128)
{
    cuuint64_t dims[2]    = {32ull, rows128};    // 32 f32 (128B) x rows
    cuuint64_t strides[1] = {128ull};
    cuuint32_t box[2]     = {32u, 128u};         // 128B x 128 rows = 16 KB tile
    cuuint32_t es[2]      = {1u, 1u};
    CUresult r = enc(m, CU_TENSOR_MAP_DATA_TYPE_FLOAT32, 2, ptr,
                     dims, strides, box, es,
                     CU_TENSOR_MAP_INTERLEAVE_NONE,
                     CU_TENSOR_MAP_SWIZZLE_128B,
                     CU_TENSOR_MAP_L2_PROMOTION_L2_128B,
                     CU_TENSOR_MAP_FLOAT_OOB_FILL_NONE);
    return r == CUDA_SUCCESS;
}

extern "C" void kernel_launch(void* const* d_in, const int* in_sizes, int n_in,
                              void* d_out, int out_size)
{
    // metadata order: t (scalar, unused), input (B*16 f32), a(4), b(4), c(4)
    const float4* in = (const float4*)d_in[1];
    const float*  a  = (const float*)d_in[2];
    const float*  b  = (const float*)d_in[3];
    const float*  c  = (const float*)d_in[4];
    float4* out = (float4*)d_out;

    const int n = in_sizes[1] / 16;                       // rows
    const int ntiles = n / TILE_ROWS;
    const unsigned long long rows128 = (unsigned long long)in_sizes[1] / 32ull;

    EncodeTiledFn enc = nullptr;
    cudaDriverEntryPointQueryResult qs;
    void* fn = nullptr;
    if (cudaGetDriverEntryPoint("cuTensorMapEncodeTiled", &fn,
                                cudaEnableDefault, &qs) == cudaSuccess &&
        qs == cudaDriverEntryPointSuccess && fn) {
        enc = (EncodeTiledFn)fn;
    }

    if (enc && ntiles > 0) {
        CUtensorMap tin, tout;
        bool ok = build_map(enc, &tin,  (void*)d_in[1], rows128);
        ok     &= build_map(enc, &tout, (void*)d_out,   rows128);
        if (ok) {
            const int max_ctas = 6 * 148;    // 6 CTAs/SM
            int grid = max_ctas < ntiles ? max_ctas : ntiles;
            quad_pipe_kernel<<<grid, 256, SMEM_DYN>>>(tin, tout, in, out,
                                                      a, b, c, n, ntiles);
            return;
        }
    }
    const int blocks = (n + 255) / 256;
    quad_dyn_kernel<<<blocks, 256>>>(in, out, a, b, c, n);
}

// round 8
// speedup vs baseline: 1.1377x; 1.1377x over previous
#include <cuda_runtime.h>
#include <cuda.h>
#include <math.h>

// QuadrotorDynamics: per-row map over (B,16) f32.
// Input row:  [0:3]=ang, [3:6]=pos(unused), [6:9]=rate, [9:12]=vel, [12:16]=cmd
// Output row: [0:3]=ang_dot, [3:6]=vel, [6:9]=rate_dot, [9:12]=vel_dot, [12:16]=0
//
// One 256-row tile per CTA, TMA load -> in-place compute -> TMA store.
// Latency hiding comes from 6 resident CTAs/SM overlapping their chains.
// Fast-math trig for phi/psi (numerators only); PRECISE sincosf for theta
// because cos(theta) is a denominator (|theta-pi/2|~1e-5 rows blow up
// __sincosf's 3.6e-7 abs error to ~3% rel -> fails 1e-3).

#define C_L      0.17f
#define C_MASS   0.68f
#define C_DARM   0.016f
#define C_KT     0.1f
#define C_KR     0.1f
#define C_IXX    0.007f
#define C_IYY    0.007f
#define C_IZZ    0.012f
#define C_GZ     9.8067f
#define C_707L   (0.707f * C_L)

#define TILE_ROWS   256
#define TILE_BYTES  16384u

// float4-index swizzle == TMA SWIZZLE_128B layout (float4 j of 128B-row r
// goes to j ^ (r&7)).
__device__ __forceinline__ int sw(int idx) { return idx ^ ((idx >> 3) & 7); }

__device__ __forceinline__ void compute_row(
    const float4 x0, const float4 x1, const float4 x2, const float4 x3,
    float a0, float a1, float a2, float a3,
    float b0, float b1, float b2, float b3,
    float c0, float c1_, float c2_, float c3_,
    float4& o0, float4& o1, float4& o2)
{
    // thrusts = a*cmd^2 + b*cmd + c
    const float t0 = fmaf(fmaf(a0, x3.x, b0), x3.x, c0);
    const float t1 = fmaf(fmaf(a1, x3.y, b1), x3.y, c1_);
    const float t2 = fmaf(fmaf(a2, x3.z, b2), x3.z, c2_);
    const float t3 = fmaf(fmaf(a3, x3.w, b3), x3.w, c3_);

    // torques = TORQUE_MAT @ thrusts (constants folded)
    const float tqT = t0 + t1 + t2 + t3;
    const float tq1 = C_707L * ((t0 + t3) - (t1 + t2));
    const float tq2 = C_707L * ((t2 + t3) - (t0 + t1));
    const float tq3 = C_DARM * ((t1 + t3) - (t0 + t2));

    float s_phi, c_phi, s_th, c_th, s_psi, c_psi;
    __sincosf(x0.x, &s_phi, &c_phi);    // phi: numerators only -> fast OK
    sincosf(x0.y, &s_th,  &c_th);       // theta: denominator -> PRECISE
    __sincosf(x0.z, &s_psi, &c_psi);    // psi: bounded products -> fast OK

    const float p = x1.z, q = x1.w, r = x2.x;
    const float vx = x2.y, vy = x2.z, vz = x2.w;

    // ang_dot = inv(Mm) @ rate, closed form (det(Mm) = c_th)
    const float y2 = __fdividef(fmaf(s_phi, q, c_phi * r), c_th);
    const float y1 = c_phi * q - s_phi * r;
    const float y0 = fmaf(s_phi, y2, p);

    // rbi third column
    const float z0 = fmaf(c_phi * c_psi, s_th,  s_phi * s_psi);
    const float z1 = fmaf(c_phi * s_psi, s_th, -s_phi * c_psi);
    const float z2 = c_th * c_phi;

    // vel_dot = rbi[:,2]*(T/m) - KT*vel - GRAV
    const float Tm  = tqT * (1.0f / C_MASS);
    const float vd0 = fmaf(z0, Tm, -C_KT * vx);
    const float vd1 = fmaf(z1, Tm, -C_KT * vy);
    const float vd2 = fmaf(z2, Tm, -C_KT * vz) - C_GZ;

    // rate_dot = I_inv @ (tau - w x (I w) - KR*w)   (diagonal I)
    const float rd0 = (tq1 - q * r * (C_IZZ - C_IYY) - C_KR * p) * (1.0f / C_IXX);
    const float rd1 = (tq2 - r * p * (C_IXX - C_IZZ) - C_KR * q) * (1.0f / C_IYY);
    const float rd2 = (tq3 - p * q * (C_IYY - C_IXX) - C_KR * r) * (1.0f / C_IZZ);

    o0 = make_float4(y0,  y1,  y2,  vx);
    o1 = make_float4(vy,  vz,  rd0, rd1);
    o2 = make_float4(rd2, vd0, vd1, vd2);
}

// mbarrier wait with HW-sleep suspend hint.
__device__ __forceinline__ void mbar_wait(unsigned mb, unsigned phase)
{
    unsigned done;
    do {
        asm volatile("{\n\t.reg .pred p;\n\t"
                     "mbarrier.try_wait.parity.acquire.cta.shared::cta.b64 p, [%1], %2, 0x989680;\n\t"
                     "selp.b32 %0, 1, 0, p;\n\t}"
                     : "=r"(done) : "r"(mb), "r"(phase) : "memory");
    } while (!done);
}

__global__ void __launch_bounds__(256)
quad_tma_kernel(const __grid_constant__ CUtensorMap tmap_in,
                const __grid_constant__ CUtensorMap tmap_out,
                const float4* __restrict__ in,
                float4* __restrict__ out,
                const float* __restrict__ ga,
                const float* __restrict__ gb,
                const float* __restrict__ gc,
                int n)
{
    __shared__ alignas(1024) float4 s[1024];   // 16 KB tile
    __shared__ uint64_t mbar;

    const int tid = threadIdx.x;
    const int row0 = blockIdx.x << 8;
    const int rows_here = min(256, n - row0);

    const float a0 = __ldg(&ga[0]), a1 = __ldg(&ga[1]), a2 = __ldg(&ga[2]), a3 = __ldg(&ga[3]);
    const float b0 = __ldg(&gb[0]), b1 = __ldg(&gb[1]), b2 = __ldg(&gb[2]), b3 = __ldg(&gb[3]);
    const float c0 = __ldg(&gc[0]), c1 = __ldg(&gc[1]), c2 = __ldg(&gc[2]), c3 = __ldg(&gc[3]);

    if (rows_here == 256) {
        // ---- TMA path (full tile) ----
        const unsigned smem_tile = (unsigned)__cvta_generic_to_shared(s);
        const unsigned smem_mbar = (unsigned)__cvta_generic_to_shared(&mbar);
        const int c1r = blockIdx.x << 7;       // 128B-row coordinate

        if (tid == 0) {
            asm volatile("mbarrier.init.shared.b64 [%0], 1;" :: "r"(smem_mbar) : "memory");
            asm volatile("fence.proxy.async.shared::cta;" ::: "memory");
            asm volatile("mbarrier.arrive.expect_tx.shared.b64 _, [%0], %1;"
                         :: "r"(smem_mbar), "r"(TILE_BYTES) : "memory");
            asm volatile("cp.async.bulk.tensor.2d.shared::cta.global.tile.mbarrier::complete_tx::bytes"
                         " [%0], [%1, {%2, %3}], [%4];"
                         :: "r"(smem_tile), "l"(&tmap_in), "r"(0), "r"(c1r), "r"(smem_mbar)
                         : "memory");
        }
        __syncthreads();               // mbar init visible to all waiters
        mbar_wait(smem_mbar, 0u);

        {
            const int i4 = tid << 2;
            const float4 x0 = s[sw(i4 + 0)];
            const float4 x1 = s[sw(i4 + 1)];
            const float4 x2 = s[sw(i4 + 2)];
            const float4 x3 = s[sw(i4 + 3)];
            float4 o0, o1, o2;
            compute_row(x0, x1, x2, x3, a0,a1,a2,a3, b0,b1,b2,b3, c0,c1,c2,c3, o0, o1, o2);
            s[sw(i4 + 0)] = o0;
            s[sw(i4 + 1)] = o1;
            s[sw(i4 + 2)] = o2;
            s[sw(i4 + 3)] = make_float4(0.0f, 0.0f, 0.0f, 0.0f);
        }
        __syncthreads();

        if (tid == 0) {
            asm volatile("fence.proxy.async.shared::cta;" ::: "memory");
            asm volatile("cp.async.bulk.tensor.2d.global.shared::cta.tile.bulk_group"
                         " [%0, {%1, %2}], [%3];"
                         :: "l"(&tmap_out), "r"(0), "r"(c1r), "r"(smem_tile)
                         : "memory");
            asm volatile("cp.async.bulk.commit_group;" ::: "memory");
            // keep smem alive until the TMA engine has read it; global
            // visibility is guaranteed at kernel boundary (CUTLASS pattern).
            asm volatile("cp.async.bulk.wait_group.read 0;" ::: "memory");
        }
        // no trailing sync: other threads may exit; CTA teardown waits for all.
    } else {
        // ---- fallback path (partial last tile): LDG/STS staging ----
        const int q_here = rows_here << 2;
        const int gbase = row0 << 2;

        #pragma unroll
        for (int k = 0; k < 4; k++) {
            int idx = tid + (k << 8);
            if (idx < q_here) s[sw(idx)] = in[gbase + idx];
        }
        __syncthreads();

        if (tid < rows_here) {
            const int i4 = tid << 2;
            const float4 x0 = s[sw(i4 + 0)];
            const float4 x1 = s[sw(i4 + 1)];
            const float4 x2 = s[sw(i4 + 2)];
            const float4 x3 = s[sw(i4 + 3)];
            float4 o0, o1, o2;
            compute_row(x0, x1, x2, x3, a0,a1,a2,a3, b0,b1,b2,b3, c0,c1,c2,c3, o0, o1, o2);
            s[sw(i4 + 0)] = o0;
            s[sw(i4 + 1)] = o1;
            s[sw(i4 + 2)] = o2;
            s[sw(i4 + 3)] = make_float4(0.0f, 0.0f, 0.0f, 0.0f);
        }
        __syncthreads();

        #pragma unroll
        for (int k = 0; k < 4; k++) {
            int idx = tid + (k << 8);
            if (idx < q_here) out[gbase + idx] = s[sw(idx)];
        }
    }
}

// ---------------------------------------------------------------------------
// Fallback (no TMA): smem-staged kernel.
// ---------------------------------------------------------------------------
__global__ void __launch_bounds__(256)
quad_dyn_kernel(const float4* __restrict__ in,
                float4* __restrict__ out,
                const float* __restrict__ ga,
                const float* __restrict__ gb,
                const float* __restrict__ gc,
                int n)
{
    __shared__ float4 s[1024];
    const int tid = threadIdx.x;
    const int row0 = blockIdx.x << 8;
    const int rows_here = min(256, n - row0);
    const int q_here = rows_here << 2;
    const int gbase = row0 << 2;

    const float a0 = __ldg(&ga[0]), a1 = __ldg(&ga[1]), a2 = __ldg(&ga[2]), a3 = __ldg(&ga[3]);
    const float b0 = __ldg(&gb[0]), b1 = __ldg(&gb[1]), b2 = __ldg(&gb[2]), b3 = __ldg(&gb[3]);
    const float c0 = __ldg(&gc[0]), c1 = __ldg(&gc[1]), c2 = __ldg(&gc[2]), c3 = __ldg(&gc[3]);

    #pragma unroll
    for (int k = 0; k < 4; k++) {
        int idx = tid + (k << 8);
        if (idx < q_here) s[sw(idx)] = in[gbase + idx];
    }
    __syncthreads();

    if (tid < rows_here) {
        const int i4 = tid << 2;
        const float4 x0 = s[sw(i4 + 0)];
        const float4 x1 = s[sw(i4 + 1)];
        const float4 x2 = s[sw(i4 + 2)];
        const float4 x3 = s[sw(i4 + 3)];
        float4 o0, o1, o2;
        compute_row(x0, x1, x2, x3, a0,a1,a2,a3, b0,b1,b2,b3, c0,c1,c2,c3, o0, o1, o2);
        s[sw(i4 + 0)] = o0;
        s[sw(i4 + 1)] = o1;
        s[sw(i4 + 2)] = o2;
        s[sw(i4 + 3)] = make_float4(0.0f, 0.0f, 0.0f, 0.0f);
    }
    __syncthreads();

    #pragma unroll
    for (int k = 0; k < 4; k++) {
        int idx = tid + (k << 8);
        if (idx < q_here) out[gbase + idx] = s[sw(idx)];
    }
}

// ---------------------------------------------------------------------------
// Host side
// ---------------------------------------------------------------------------
typedef CUresult (*EncodeTiledFn)(
    CUtensorMap*, CUtensorMapDataType, cuuint32_t, void*,
    const cuuint64_t*, const cuuint64_t*, const cuuint32_t*, const cuuint32_t*,
    CUtensorMapInterleave, CUtensorMapSwizzle, CUtensorMapL2promotion,
    CUtensorMapFloatOOBfill);

static bool build_map(EncodeTiledFn enc, CUtensorMap* m, void* ptr,
                      unsigned long long rows128)
{
    cuuint64_t dims[2]    = {32ull, rows128};    // 32 f32 (128B) x rows
    cuuint64_t strides[1] = {128ull};
    cuuint32_t box[2]     = {32u, 128u};         // 128B x 128 rows = 16 KB tile
    cuuint32_t es[2]      = {1u, 1u};
    CUresult r = enc(m, CU_TENSOR_MAP_DATA_TYPE_FLOAT32, 2, ptr,
                     dims, strides, box, es,
                     CU_TENSOR_MAP_INTERLEAVE_NONE,
                     CU_TENSOR_MAP_SWIZZLE_128B,
                     CU_TENSOR_MAP_L2_PROMOTION_L2_128B,
                     CU_TENSOR_MAP_FLOAT_OOB_FILL_NONE);
    return r == CUDA_SUCCESS;
}

extern "C" void kernel_launch(void* const* d_in, const int* in_sizes, int n_in,
                              void* d_out, int out_size)
{
    // metadata order: t (scalar, unused), input (B*16 f32), a(4), b(4), c(4)
    const float4* in = (const float4*)d_in[1];
    const float*  a  = (const float*)d_in[2];
    const float*  b  = (const float*)d_in[3];
    const float*  c  = (const float*)d_in[4];
    float4* out = (float4*)d_out;

    const int n = in_sizes[1] / 16;                   // rows
    const unsigned long long rows128 = (unsigned long long)in_sizes[1] / 32ull;
    const int blocks = (n + 255) / 256;

    EncodeTiledFn enc = nullptr;
    cudaDriverEntryPointQueryResult qs;
    void* fn = nullptr;
    if (cudaGetDriverEntryPoint("cuTensorMapEncodeTiled", &fn,
                                cudaEnableDefault, &qs) == cudaSuccess &&
        qs == cudaDriverEntryPointSuccess && fn) {
        enc = (EncodeTiledFn)fn;
    }

    if (enc) {
        CUtensorMap tin, tout;
        bool ok = build_map(enc, &tin,  (void*)d_in[1], rows128);
        ok     &= build_map(enc, &tout, (void*)d_out,   rows128);
        if (ok) {
            quad_tma_kernel<<<blocks, 256>>>(tin, tout, in, out, a, b, c, n);
            return;
        }
    }
    quad_dyn_kernel<<<blocks, 256>>>(in, out, a, b, c, n);
}